// round 11
// baseline (speedup 1.0000x reference)
#include <cuda_runtime.h>
#include <math.h>

// Problem constants (must match reference)
#define BB 16
#define HH 120
#define WW 160
#define WG 16               // w-columns per block (4 float4 quads)
#define NT 512              // 16 warps; grid=160 -> 2560 warps, ~1-2 blocks/SM, one wave
#define DD 401              // int(8000/20)+1
#define NQ (HH * (WG/4))    // 480 depth quads (LDG.128) per block
#define NV4 ((WG * DD) / 4) // 1604 float4 in the block's output span
#define DEPTH_MAX 8000.0f
#define INV_BIN   (1.0f / 20.0f)
#define BIN_SIZE  20.0f
#define ZERO_EPS  1e-06f
#define SIG_EPS   (0.5f + 1e-08f)

// fp32 sparsity: the Gaussian underflows to exactly 0 unless |k*20 - d| < ~7.2;
// bins are 20 apart -> only the rounded-nearest bin k = round(d/20) can be
// nonzero. For valid d in (eps, 8000], k in [0,400]: no clamp. (d>eps && d<=max)
// also rejects NaN/Inf.
//
// Frame: proven r5 structure (gmem zero overlapped with depth LDG, one
// bar.sync = exec + membar.cta, fire-and-forget RED.E.ADD.F32, no smem,
// no tail store) -- but with 4x fewer, 4x fatter blocks to cut CTA-ramp
// overhead, the one axis with a measured positive gradient (2560 blocks:
// 7.0us -> 640 blocks: 5.34us).

__global__ void __launch_bounds__(NT)
dim_hist_kernel(const float* __restrict__ depth, float* __restrict__ out)
{
    const int blk = blockIdx.x;              // 0 .. 159
    const int b   = blk / (WW / WG);         // /10
    const int w0  = (blk - b * (WW / WG)) * WG;
    const int tid = threadIdx.x;

    // ---- depth: one LDG.128 per thread (tid<480), issued first ----
    // quad q -> h = q>>2, wq = q&3 ; covers pixels w0+wq*4 .. +3 (16B aligned)
    float4 d4 = make_float4(-1.f, -1.f, -1.f, -1.f);
    if (tid < NQ)
        d4 = *(const float4*)(depth + ((size_t)b * HH + (tid >> 2)) * WW
                              + w0 + (tid & 3) * 4);

    // ---- zero this block's private output span: 1604 STG.128 ----
    float* ospan = out + ((size_t)b * WW + w0) * DD;             // 16B-aligned
    float4* o4 = (float4*)ospan;
    const float4 z4 = make_float4(0.f, 0.f, 0.f, 0.f);
    o4[tid]          = z4;                    // tid < 512 < 1604
    o4[tid + NT]     = z4;                    // < 1024
    o4[tid + 2*NT]   = z4;                    // < 1536
    if (tid + 3*NT < NV4) o4[tid + 3*NT] = z4;   // threads 0..67

    __syncthreads();   // exec + membar.cta: zeros visible before our atomics

    const float inv_sig = 1.0f / SIG_EPS;                 // 1/(sigma+eps)
    const float norm    = 0.3989422804014327f * inv_sig;  // 1/((sigma+eps)*sqrt(2pi))

    // ---- scatter: 4 pixels per loading thread; REDG is no-return ----
    if (tid < NQ) {
        float* qbase = ospan + ((tid & 3) * 4) * DD;      // bin row for w = w0+wq*4
        const float dv[4] = {d4.x, d4.y, d4.z, d4.w};
        #pragma unroll
        for (int j = 0; j < 4; ++j) {
            float d = dv[j];
            if (d > ZERO_EPS && d <= DEPTH_MAX) {         // also rejects NaN/Inf
                int k   = __float2int_rn(d * INV_BIN);    // nearest bin, [0,400]
                float z = ((float)k * BIN_SIZE - d) * inv_sig;
                float g = __expf(-0.5f * z * z) * norm;
                if (g != 0.0f) atomicAdd(qbase + j * DD + k, g);  // RED.E.ADD.F32
            }
        }
    }
}

extern "C" void kernel_launch(void* const* d_in, const int* in_sizes, int n_in,
                              void* d_out, int out_size)
{
    const float* depth = (const float*)d_in[0];
    float* out = (float*)d_out;
    dim_hist_kernel<<<BB * (WW / WG), NT>>>(depth, out);
}

// round 12
// speedup vs baseline: 1.3286x; 1.3286x over previous
#include <cuda_runtime.h>
#include <math.h>

// Problem constants (must match reference)
#define BB 16
#define HH 120
#define WW 160
#define DD 401              // int(8000/20)+1
#define WT 4                // w-tile per block
#define NT 384              // 12 warps -> 5 blocks/SM -> 640 blocks in ONE wave
#define NPIX (HH * WT)      // 480 pixels per block
#define NV4 ((WT * DD) / 4) // 401 float4 in the block's output span
#define DEPTH_MAX 8000.0f
#define INV_BIN   (1.0f / 20.0f)
#define BIN_SIZE  20.0f
#define ZERO_EPS  1e-06f
#define SIG_EPS   (0.5f + 1e-08f)

// fp32 sparsity: the Gaussian underflows to exactly 0 unless |k*20 - d| < ~7.2;
// bins are 20 apart -> only the rounded-nearest bin k = round(d/20) can be
// nonzero. For valid d in (eps, 8000], k is in [0,400]: no clamp needed.
// (d > eps && d <= max) also rejects NaN/Inf.
//
// FINAL (measured optimum, 5.344us kernel twice): each block owns
// out[b, w0..w0+3, :] EXCLUSIVELY. Zero that span in GMEM up front (stores
// overlap the depth LDG latency), one bar.sync (exec + membar.cta: zeros
// ordered before this block's atomics at L2), then fire-and-forget
// RED.E.ADD.F32 scatter. No smem, no second barrier, no post-sync store tail.
//
// Full calibration record (kernel-side, ncu):
//   grid sweep: 2560 blks 7.0us | 640 blks 5.34us(x2) | 160 blks 5.92us
//   NT sweep (grid=640): 256: 5.92 | 384: 5.34 | 512(two waves): 5.70
//   exp2f / unguarded-RED: 6.05 (regress) ; vectorized-LDG concentration: 5.47
//   identical-source re-bench spread: +-0.5us (plateau = launch/ramp overhead;
//   all pipes <24% of peak). Keep __expf (MUFU.EX2 fast path) + g!=0 guard.

__global__ void __launch_bounds__(NT)
dim_hist_kernel(const float* __restrict__ depth, float* __restrict__ out)
{
    const int blk = blockIdx.x;              // 0 .. 639
    const int b   = blk / (WW / WT);
    const int w0  = (blk - b * (WW / WT)) * WT;
    const int tid = threadIdx.x;

    // ---- depth prefetch first: LDG latency overlaps the zeroing stores ----
    // pixel p -> h = p>>2, wi = p&3 ; consecutive tid -> consecutive w
    const float* dbase = depth + (size_t)b * HH * WW + w0;
    float d0 = -1.0f, d1 = -1.0f;
    d0 = __ldg(dbase + (tid >> 2) * WW + (tid & 3));            // tid < 480 always
    {
        int p2 = tid + NT;                                       // 384..767
        if (p2 < NPIX) d1 = __ldg(dbase + (p2 >> 2) * WW + (p2 & 3));
    }

    // ---- zero this block's private output span: 401 STG.128 ----
    float* ospan = out + ((size_t)b * WW + w0) * DD;             // 16B-aligned
    float4* o4 = (float4*)ospan;
    const float4 z4 = make_float4(0.f, 0.f, 0.f, 0.f);
    if (tid < NV4) o4[tid] = z4;
    if (tid + NT < NV4) o4[tid + NT] = z4;

    // hoisted atomic bases (pure ALU, overlaps LDG wait)
    float* abase0 = ospan + (tid & 3) * DD;
    float* abase1 = ospan + ((tid + NT) & 3) * DD;

    __syncthreads();   // exec + membar.cta: zeros visible before our atomics

    const float inv_sig = 1.0f / SIG_EPS;                 // 1/(sigma+eps)
    const float norm    = 0.3989422804014327f * inv_sig;  // 1/((sigma+eps)*sqrt(2pi))

    // ---- scatter: one EX2 + at most one no-return global atomic per pixel ----
    if (d0 > ZERO_EPS && d0 <= DEPTH_MAX) {
        int k   = __float2int_rn(d0 * INV_BIN);           // nearest bin, [0,400]
        float z = ((float)k * BIN_SIZE - d0) * inv_sig;
        float g = __expf(-0.5f * z * z) * norm;
        if (g != 0.0f) atomicAdd(abase0 + k, g);          // RED.E.ADD.F32
    }
    if (d1 > ZERO_EPS && d1 <= DEPTH_MAX) {
        int k   = __float2int_rn(d1 * INV_BIN);
        float z = ((float)k * BIN_SIZE - d1) * inv_sig;
        float g = __expf(-0.5f * z * z) * norm;
        if (g != 0.0f) atomicAdd(abase1 + k, g);
    }
}

extern "C" void kernel_launch(void* const* d_in, const int* in_sizes, int n_in,
                              void* d_out, int out_size)
{
    const float* depth = (const float*)d_in[0];
    float* out = (float*)d_out;
    dim_hist_kernel<<<(BB * WW) / WT, NT>>>(depth, out);
}